// round 1
// baseline (speedup 1.0000x reference)
#include <cuda_runtime.h>
#include <math.h>

#define N 8192
#define D 32
#define NB 64          // number of 128-blocks
#define B 128          // cholesky block
#define GAMMA 0.03125f
#define REG 1e-3f

// ---------------- device scratch (static globals; no allocation) ----------------
__device__ float g_A[(size_t)N * N];          // 256 MB gram / L factor
__device__ float g_invL[NB * B * B];          // 4 MB inverses of diag blocks
__device__ float g_xx[N];                     // train row norms
__device__ float g_r[N];                      // working rhs (forward)
__device__ float g_zsol[N];                   // z after forward solve / working (backward)
__device__ float g_alpha[N];                  // solution

// ---------------- prep: norms + rhs init ----------------
__global__ void prep_kernel(const float* __restrict__ Xtr, const float* __restrict__ y) {
    int i = blockIdx.x * 256 + threadIdx.x;
    float s = 0.f;
#pragma unroll
    for (int dg = 0; dg < 8; dg++) {
        float4 v = *(const float4*)(Xtr + (size_t)i * D + dg * 4);
        s += v.x * v.x + v.y * v.y + v.z * v.z + v.w * v.w;
    }
    g_xx[i] = s;
    g_r[i] = y[i];
}

// ---------------- build full gram matrix ----------------
__global__ void __launch_bounds__(256, 2) build_kernel(const float* __restrict__ Xtr) {
    __shared__ float sXi[32 * 132];
    __shared__ float sXj[32 * 132];
    __shared__ float sxxi[128], sxxj[128];
    int tid = threadIdx.x;
    int bi = blockIdx.y, bj = blockIdx.x;

#pragma unroll
    for (int i = 0; i < 4; i++) {
        int f = tid + i * 256;          // 0..1023
        int r = f >> 3;                 // 0..127
        int dg = (f & 7) << 2;          // 0..28
        float4 v = *(const float4*)(Xtr + (size_t)(bi * B + r) * D + dg);
        sXi[(dg + 0) * 132 + r] = v.x; sXi[(dg + 1) * 132 + r] = v.y;
        sXi[(dg + 2) * 132 + r] = v.z; sXi[(dg + 3) * 132 + r] = v.w;
        float4 w = *(const float4*)(Xtr + (size_t)(bj * B + r) * D + dg);
        sXj[(dg + 0) * 132 + r] = w.x; sXj[(dg + 1) * 132 + r] = w.y;
        sXj[(dg + 2) * 132 + r] = w.z; sXj[(dg + 3) * 132 + r] = w.w;
    }
    if (tid < 128) { sxxi[tid] = g_xx[bi * B + tid]; sxxj[tid] = g_xx[bj * B + tid]; }
    __syncthreads();

    int tm = tid >> 4, tn = tid & 15;
    float acc[8][8];
#pragma unroll
    for (int i = 0; i < 8; i++)
#pragma unroll
        for (int j = 0; j < 8; j++) acc[i][j] = 0.f;

#pragma unroll
    for (int d = 0; d < 32; d++) {
        float a[8], b[8];
        *(float4*)(a)     = *(const float4*)(&sXi[d * 132 + tm * 8]);
        *(float4*)(a + 4) = *(const float4*)(&sXi[d * 132 + tm * 8 + 4]);
        *(float4*)(b)     = *(const float4*)(&sXj[d * 132 + tn * 8]);
        *(float4*)(b + 4) = *(const float4*)(&sXj[d * 132 + tn * 8 + 4]);
#pragma unroll
        for (int i = 0; i < 8; i++)
#pragma unroll
            for (int j = 0; j < 8; j++) acc[i][j] += a[i] * b[j];
    }

#pragma unroll
    for (int i = 0; i < 8; i++) {
        int li = tm * 8 + i;
        int gi = bi * B + li;
        float v[8];
#pragma unroll
        for (int j = 0; j < 8; j++) {
            int lj = tn * 8 + j;
            int gj = bj * B + lj;
            float sq = sxxi[li] + sxxj[lj] - 2.f * acc[i][j];
            sq = fmaxf(sq, 0.f);
            float val = __expf(-GAMMA * sq);
            if (gi == gj) val += REG;
            v[j] = val;
        }
        float* cp = g_A + (size_t)gi * N + bj * B + tn * 8;
        *(float4*)(cp)     = make_float4(v[0], v[1], v[2], v[3]);
        *(float4*)(cp + 4) = make_float4(v[4], v[5], v[6], v[7]);
    }
}

// ---------------- diag block: cholesky + inverse ----------------
#define POTF_SMEM (2 * 128 * 129 * 4)
__global__ void __launch_bounds__(256, 1) potf_kernel(int kb) {
    extern __shared__ float sm[];
    float* sL = sm;                 // [128][129]
    float* sW = sm + 128 * 129;     // transposed inverse: sW[c*129 + r]
    __shared__ float sID[128];      // 1/L[c][c]
    int tid = threadIdx.x;
    size_t base = (size_t)(kb * B) * N + (size_t)kb * B;

    for (int idx = tid; idx < B * B; idx += 256) {
        int r = idx >> 7, c = idx & 127;
        sL[r * 129 + c] = g_A[base + (size_t)r * N + c];
    }
    __syncthreads();

    int tr = tid & 31, tj = tid >> 5;  // 32 x 8
    for (int c = 0; c < B; c++) {
        float piv = sL[c * 129 + c];
        float inv = rsqrtf(piv);
        if (tid == 0) sID[c] = inv;
        __syncthreads();                      // all read pivot before scaling
        if (tid < B - c) sL[(c + tid) * 129 + c] *= inv;   // includes diag -> sqrt
        __syncthreads();
        if (c < B - 1) {
            for (int r = c + 1 + tr; r < B; r += 32) {
                float lrc = sL[r * 129 + c];
                for (int j = c + 1 + tj; j <= r; j += 8)
                    sL[r * 129 + j] -= lrc * sL[j * 129 + c];
            }
        }
        __syncthreads();
    }

    // inverse of L via per-column forward substitution (thread c -> column c)
    if (tid < 128) {
        int c = tid;
        float* wc = sW + c * 129;
        for (int r = 0; r < c; r++) wc[r] = 0.f;
        wc[c] = sID[c];
        for (int r = c + 1; r < B; r++) {
            const float* Lr = sL + r * 129;
            float a0 = 0.f, a1 = 0.f, a2 = 0.f, a3 = 0.f;
            int j = c;
            for (; j + 3 < r; j += 4) {
                a0 += Lr[j] * wc[j];     a1 += Lr[j + 1] * wc[j + 1];
                a2 += Lr[j + 2] * wc[j + 2]; a3 += Lr[j + 3] * wc[j + 3];
            }
            for (; j < r; j++) a0 += Lr[j] * wc[j];
            wc[r] = -((a0 + a1) + (a2 + a3)) * sID[r];
        }
    }
    __syncthreads();

    // write back L (full block) and W (row-major, zero upper)
    for (int idx = tid; idx < B * B; idx += 256) {
        int r = idx >> 7, c = idx & 127;
        g_A[base + (size_t)r * N + c] = sL[r * 129 + c];
        g_invL[kb * (B * B) + idx] = sW[c * 129 + r];
    }
}

// ---------------- generic 128x128x128 tile C (op)= A * B^T ----------------
__device__ __forceinline__ void tile_gemm_nt(const float* __restrict__ A, int lda,
                                             const float* __restrict__ Bm, int ldb,
                                             float* __restrict__ C, int ldc, bool sub) {
    __shared__ float As[16 * 132];
    __shared__ float Bs[16 * 132];
    float acc[8][8];
#pragma unroll
    for (int i = 0; i < 8; i++)
#pragma unroll
        for (int j = 0; j < 8; j++) acc[i][j] = 0.f;

    int tid = threadIdx.x;
    int tm = tid >> 4, tn = tid & 15;
    int lr = tid >> 2;             // 0..63
    int lk = (tid & 3) << 2;       // 0,4,8,12

    for (int kk = 0; kk < 128; kk += 16) {
#pragma unroll
        for (int h = 0; h < 2; h++) {
            int r = lr + (h << 6);
            float4 va = *(const float4*)(A + (size_t)r * lda + kk + lk);
            As[(lk + 0) * 132 + r] = va.x; As[(lk + 1) * 132 + r] = va.y;
            As[(lk + 2) * 132 + r] = va.z; As[(lk + 3) * 132 + r] = va.w;
            float4 vb = *(const float4*)(Bm + (size_t)r * ldb + kk + lk);
            Bs[(lk + 0) * 132 + r] = vb.x; Bs[(lk + 1) * 132 + r] = vb.y;
            Bs[(lk + 2) * 132 + r] = vb.z; Bs[(lk + 3) * 132 + r] = vb.w;
        }
        __syncthreads();
#pragma unroll
        for (int k = 0; k < 16; k++) {
            float a[8], b[8];
            *(float4*)(a)     = *(const float4*)(&As[k * 132 + tm * 8]);
            *(float4*)(a + 4) = *(const float4*)(&As[k * 132 + tm * 8 + 4]);
            *(float4*)(b)     = *(const float4*)(&Bs[k * 132 + tn * 8]);
            *(float4*)(b + 4) = *(const float4*)(&Bs[k * 132 + tn * 8 + 4]);
#pragma unroll
            for (int i = 0; i < 8; i++)
#pragma unroll
                for (int j = 0; j < 8; j++) acc[i][j] += a[i] * b[j];
        }
        __syncthreads();
    }

#pragma unroll
    for (int i = 0; i < 8; i++) {
        int r = tm * 8 + i;
        float4* cp = (float4*)(C + (size_t)r * ldc + tn * 8);
        if (sub) {
            float4 c0 = cp[0], c1 = cp[1];
            c0.x -= acc[i][0]; c0.y -= acc[i][1]; c0.z -= acc[i][2]; c0.w -= acc[i][3];
            c1.x -= acc[i][4]; c1.y -= acc[i][5]; c1.z -= acc[i][6]; c1.w -= acc[i][7];
            cp[0] = c0; cp[1] = c1;
        } else {
            cp[0] = make_float4(acc[i][0], acc[i][1], acc[i][2], acc[i][3]);
            cp[1] = make_float4(acc[i][4], acc[i][5], acc[i][6], acc[i][7]);
        }
    }
}

// panel trsm:  P := P * W^T   (W = L_kk^{-1}, in-place)
__global__ void __launch_bounds__(256, 2) trsm_kernel(int kb) {
    int rb = kb + 1 + blockIdx.x;
    float* Apan = g_A + (size_t)(rb * B) * N + (size_t)kb * B;
    const float* W = g_invL + kb * (B * B);
    tile_gemm_nt(Apan, N, W, B, Apan, N, false);
}

// trailing syrk:  C(ib,jb) -= P(ib) * P(jb)^T  over lower triangle
__global__ void __launch_bounds__(256, 2) syrk_kernel(int kb) {
    int p = blockIdx.x;
    float pf = sqrtf(8.f * (float)p + 1.f);
    int ti = (int)((pf - 1.f) * 0.5f);
    while ((ti + 1) * (ti + 2) / 2 <= p) ti++;
    while (ti * (ti + 1) / 2 > p) ti--;
    int tj = p - ti * (ti + 1) / 2;
    int ib = kb + 1 + ti, jb = kb + 1 + tj;
    tile_gemm_nt(g_A + (size_t)(ib * B) * N + (size_t)kb * B, N,
                 g_A + (size_t)(jb * B) * N + (size_t)kb * B, N,
                 g_A + (size_t)(ib * B) * N + (size_t)jb * B, N, true);
}

// ---------------- blocked forward solve:  L z = y ----------------
__global__ void fwd_step(int kb) {
    __shared__ float sr[128], sz[128];
    int t = threadIdx.x;
    sr[t] = g_r[kb * B + t];
    __syncthreads();
    const float* W = g_invL + kb * (B * B);
    float acc = 0.f;
#pragma unroll 8
    for (int j = 0; j < B; j += 4) {
        float4 w = *(const float4*)(W + t * B + j);
        acc += w.x * sr[j] + w.y * sr[j + 1] + w.z * sr[j + 2] + w.w * sr[j + 3];
    }
    sz[t] = acc;
    __syncthreads();
    if (blockIdx.x == 0) { g_zsol[kb * B + t] = sz[t]; return; }
    int rb = kb + blockIdx.x;                       // kb+1 .. 63
    const float* Lr = g_A + (size_t)(rb * B + t) * N + (size_t)kb * B;
    float a = 0.f;
#pragma unroll 8
    for (int j = 0; j < B; j += 4) {
        float4 l = *(const float4*)(Lr + j);
        a += l.x * sz[j] + l.y * sz[j + 1] + l.z * sz[j + 2] + l.w * sz[j + 3];
    }
    g_r[rb * B + t] -= a;
}

// ---------------- blocked backward solve:  L^T alpha = z ----------------
__global__ void bwd_step(int kb) {
    __shared__ float sr[128], sz[128];
    int t = threadIdx.x;
    sr[t] = g_zsol[kb * B + t];
    __syncthreads();
    const float* W = g_invL + kb * (B * B);
    float acc = 0.f;
#pragma unroll 8
    for (int r = 0; r < B; r++) acc += W[r * B + t] * sr[r];   // alpha = W^T r
    sz[t] = acc;
    __syncthreads();
    if (blockIdx.x == 0) { g_alpha[kb * B + t] = sz[t]; return; }
    int jb = blockIdx.x - 1;                        // 0 .. kb-1
    float a = 0.f;
#pragma unroll 8
    for (int r = 0; r < B; r++)
        a += g_A[(size_t)(kb * B + r) * N + (size_t)jb * B + t] * sz[r];
    g_zsol[jb * B + t] -= a;
}

// ---------------- fused predict: out = exp(-g*d2(Xte, Xtr)) @ alpha ----------------
__global__ void __launch_bounds__(256, 2) predict_kernel(const float* __restrict__ Xte,
                                                         const float* __restrict__ Xtr,
                                                         float* __restrict__ out) {
    __shared__ float sTr[32 * 132];   // transposed chunk sTr[d][p]
    __shared__ float sAl[128], sXX[128];
    __shared__ float sRed[256];
    int tid = threadIdx.x;
    int rl = tid >> 3, sl = tid & 7;
    int grow = blockIdx.x * 32 + rl;

    float xt[32];
#pragma unroll
    for (int dg = 0; dg < 8; dg++)
        *(float4*)(xt + dg * 4) = *(const float4*)(Xte + (size_t)grow * D + dg * 4);
    float xxt = 0.f;
#pragma unroll
    for (int d = 0; d < 32; d++) xxt += xt[d] * xt[d];

    float acc = 0.f;
    for (int ch = 0; ch < N / 128; ch++) {
        int pbase = ch * 128;
        __syncthreads();
#pragma unroll
        for (int i = 0; i < 4; i++) {
            int f = tid + i * 256;
            int p = f >> 3;
            int dg = (f & 7) << 2;
            float4 v = *(const float4*)(Xtr + (size_t)(pbase + p) * D + dg);
            sTr[(dg + 0) * 132 + p] = v.x; sTr[(dg + 1) * 132 + p] = v.y;
            sTr[(dg + 2) * 132 + p] = v.z; sTr[(dg + 3) * 132 + p] = v.w;
        }
        if (tid < 128) { sAl[tid] = g_alpha[pbase + tid]; sXX[tid] = g_xx[pbase + tid]; }
        __syncthreads();
#pragma unroll 4
        for (int i = 0; i < 16; i++) {
            int p = i * 8 + sl;
            float dot = 0.f;
#pragma unroll
            for (int d = 0; d < 32; d++) dot += xt[d] * sTr[d * 132 + p];
            float sq = fmaxf(xxt + sXX[p] - 2.f * dot, 0.f);
            acc += __expf(-GAMMA * sq) * sAl[p];
        }
    }
    sRed[rl * 8 + sl] = acc;
    __syncthreads();
    if (tid < 32) {
        float s = 0.f;
#pragma unroll
        for (int j = 0; j < 8; j++) s += sRed[tid * 8 + j];
        out[blockIdx.x * 32 + tid] = s;
    }
}

// ---------------- launcher ----------------
extern "C" void kernel_launch(void* const* d_in, const int* in_sizes, int n_in,
                              void* d_out, int out_size) {
    const float* Xtr = (const float*)d_in[0];
    const float* y   = (const float*)d_in[1];
    const float* Xte = (const float*)d_in[2];
    float* out = (float*)d_out;

    cudaFuncSetAttribute(potf_kernel, cudaFuncAttributeMaxDynamicSharedMemorySize, POTF_SMEM);

    prep_kernel<<<N / 256, 256>>>(Xtr, y);
    build_kernel<<<dim3(NB, NB), 256>>>(Xtr);

    for (int kb = 0; kb < NB; kb++) {
        potf_kernel<<<1, 256, POTF_SMEM>>>(kb);
        int nb = NB - 1 - kb;              // row-blocks below
        if (nb > 0) {
            trsm_kernel<<<nb, 256>>>(kb);
            int pairs = nb * (nb + 1) / 2;
            syrk_kernel<<<pairs, 256>>>(kb);
        }
    }

    for (int kb = 0; kb < NB; kb++)  fwd_step<<<NB - kb, 128>>>(kb);
    for (int kb = NB - 1; kb >= 0; kb--) bwd_step<<<kb + 1, 128>>>(kb);

    predict_kernel<<<N / 32, 256>>>(Xte, Xtr, out);
}